// round 12
// baseline (speedup 1.0000x reference)
#include <cuda_runtime.h>
#include <cuda_fp16.h>
#include <cstdint>

// ============================ device scratch (16B-aligned) ===============
#define N_NODES_MAX 100000
#define DFEAT 128
// each uint4 = 8 fp16
__device__ uint4 g_z_hi4[(size_t)N_NODES_MAX * DFEAT / 8];
__device__ uint4 g_z_lo4[(size_t)N_NODES_MAX * DFEAT / 8];
__device__ uint4 g_w1t4[128 * 256 / 8];      // [n][k] fp16, row = 32 uint4

// ============================ helpers ====================================
__device__ __forceinline__ void mma16816(float* d, const uint32_t* a,
                                         const uint32_t* b) {
    asm volatile(
        "mma.sync.aligned.m16n8k16.row.col.f32.f16.f16.f32 "
        "{%0,%1,%2,%3},{%4,%5,%6,%7},{%8,%9},{%0,%1,%2,%3};"
        : "+f"(d[0]), "+f"(d[1]), "+f"(d[2]), "+f"(d[3])
        : "r"(a[0]), "r"(a[1]), "r"(a[2]), "r"(a[3]), "r"(b[0]), "r"(b[1]));
}
__device__ __forceinline__ void ldsm4(uint32_t& r0, uint32_t& r1,
                                      uint32_t& r2, uint32_t& r3, uint32_t a) {
    asm volatile("ldmatrix.sync.aligned.m8n8.x4.shared.b16 {%0,%1,%2,%3}, [%4];"
                 : "=r"(r0), "=r"(r1), "=r"(r2), "=r"(r3) : "r"(a));
}
__device__ __forceinline__ uint32_t smem_u32(const void* p) {
    uint32_t a;
    asm("{ .reg .u64 t; cvta.to.shared.u64 t, %1; cvt.u32.u64 %0, t; }"
        : "=r"(a) : "l"(p));
    return a;
}
__device__ __forceinline__ void cp_cg16(uint32_t dst, const void* src) {
    asm volatile("cp.async.cg.shared.global [%0], [%1], 16;"
                 :: "r"(dst), "l"(src) : "memory");
}
__device__ __forceinline__ void cp_ca16(uint32_t dst, const void* src) {
    asm volatile("cp.async.ca.shared.global [%0], [%1], 16;"
                 :: "r"(dst), "l"(src) : "memory");
}
#define CP_COMMIT()  asm volatile("cp.async.commit_group;" ::: "memory")
#define CP_WAIT(n)   asm volatile("cp.async.wait_group %0;" :: "n"(n) : "memory")

// ============================ fused conversion kernel ====================
__global__ void convert_fused(const float4* __restrict__ z,
                              const float* __restrict__ W1,
                              int n8, int zblocks) {
    if ((int)blockIdx.x < zblocks) {
        int i = blockIdx.x * 256 + threadIdx.x;
        if (i >= n8) return;
        float4 a = z[2 * i], b = z[2 * i + 1];
        float f[8] = {a.x, a.y, a.z, a.w, b.x, b.y, b.z, b.w};
        unsigned int h[8], l[8];
#pragma unroll
        for (int j = 0; j < 8; ++j) {
            __half hb = __float2half(f[j]);
            float r = f[j] - __half2float(hb);
            __half lb = __float2half(r);
            h[j] = (unsigned int)__half_as_ushort(hb);
            l[j] = (unsigned int)__half_as_ushort(lb);
        }
        g_z_hi4[i] = make_uint4(h[0] | (h[1] << 16), h[2] | (h[3] << 16),
                                h[4] | (h[5] << 16), h[6] | (h[7] << 16));
        g_z_lo4[i] = make_uint4(l[0] | (l[1] << 16), l[2] | (l[3] << 16),
                                l[4] | (l[5] << 16), l[6] | (l[7] << 16));
    } else {
        int i = (blockIdx.x - zblocks) * 256 + threadIdx.x;  // i = k*128 + n
        if (i >= 256 * 128) return;
        int k = i >> 7, n = i & 127;
        reinterpret_cast<__half*>(g_w1t4)[n * 256 + k] = __float2half(W1[i]);
    }
}

// ============================ main kernel ================================
// SMEM tiles: 128 rows x 32 k fp16, row stride 40 halfs (80 B = 20 words)
#define TILE_BYTES 10240
#define OFF_TILES  0                    // 6 tiles (2 buf x {Ah,Al,B})
#define OFF_ROWS   (6 * TILE_BYTES)     // int[256]
#define OFF_B1     (OFF_ROWS + 1024)    // float[128]
#define OFF_W2     (OFF_B1 + 512)       // float[128]
#define OFF_RED    (OFF_W2 + 512)       // float[128][5]
#define SMEM_TOTAL (OFF_RED + 2560)

__global__ void __launch_bounds__(256, 2)
edge_mlp_hmma(const long long* __restrict__ eli64,
              const float* __restrict__ b1,
              const float* __restrict__ W2v,
              const float* __restrict__ b2,
              float* __restrict__ out,
              int n_edges)
{
    extern __shared__ char dsm[];
    int*   rows = (int*)(dsm + OFF_ROWS);
    float* s_b1 = (float*)(dsm + OFF_B1);
    float* s_w2 = (float*)(dsm + OFF_W2);
    float (*red)[5] = (float(*)[5])(dsm + OFF_RED);

    const int tid = threadIdx.x;
    const int lid = tid & 31;
    const int wid = tid >> 5;
    const int warp_m = wid >> 2;          // 0..1 -> 64 rows each
    const int warp_n = wid & 3;           // 0..3 -> 32 cols each
    const long long e0 = (long long)blockIdx.x * 128;

    // ---- index dtype detection (int64 declared, int32 possible) ----
    const int* eli32 = (const int*)eli64;
    int hi_or = eli32[1] | eli32[3] | eli32[5] | eli32[7]
              | eli32[9] | eli32[11] | eli32[13] | eli32[15];
    const bool is64 = (hi_or == 0);

    if (tid < 128) {
        long long e = e0 + tid;
        if (e >= n_edges) e = 0;
        int rs, rd;
        if (is64) { rs = (int)eli64[e]; rd = (int)eli64[(long long)n_edges + e]; }
        else      { rs = eli32[e];      rd = eli32[(long long)n_edges + e]; }
        rows[tid]       = rs;
        rows[128 + tid] = rd;
    } else {
        int h = tid - 128;
        s_b1[h] = b1[h];
        s_w2[h] = W2v[h];
    }
    __syncthreads();

    // ---- ldmatrix per-lane offsets ----
    const uint32_t sel = (uint32_t)lid >> 3;   // 0..3
    const uint32_t rA  = (uint32_t)lid & 7;
    const uint32_t aOff = ((uint32_t)warp_m * 64 + (sel & 1) * 8 + rA) * 80
                        + (sel >> 1) * 16;           // + mi*1280 + s*32
    const uint32_t bOff = ((uint32_t)warp_n * 32 + (sel >> 1) * 8 + rA) * 80
                        + (sel & 1) * 16;            // + nj*1280 + s*32

    float acc[4][4][4];
#pragma unroll
    for (int mi = 0; mi < 4; ++mi)
#pragma unroll
        for (int ni = 0; ni < 4; ++ni)
#pragma unroll
            for (int qq = 0; qq < 4; ++qq) acc[mi][ni][qq] = 0.0f;

    // gather geometry: 2 threads per row, 32B (2x16B) each
    const int gr  = tid >> 1;
    const int seg = tid & 1;
    const uint32_t smo = (uint32_t)gr * 80 + (uint32_t)seg * 32;
    const uint32_t sTiles = smem_u32(dsm + OFF_TILES);
    const uint32_t sAh0 = sTiles + smo;
    const size_t wa = (size_t)gr * 32 + (size_t)seg * 2;

    auto gather = [&](int c, int p) {
        const int half = c >> 2;
        const int czi  = (c & 3) * 4;
        const uint32_t base = sAh0 + (uint32_t)p * 3 * TILE_BYTES;
        const size_t za = (size_t)rows[half * 128 + gr] * 16 + czi + (size_t)seg * 2;
        cp_cg16(base,                   g_z_hi4 + za);
        cp_cg16(base + 16,              g_z_hi4 + za + 1);
        cp_cg16(base + TILE_BYTES,      g_z_lo4 + za);
        cp_cg16(base + TILE_BYTES + 16, g_z_lo4 + za + 1);
        const size_t wz = wa + (size_t)c * 4;
        cp_ca16(base + 2 * TILE_BYTES,      g_w1t4 + wz);
        cp_ca16(base + 2 * TILE_BYTES + 16, g_w1t4 + wz + 1);
    };

    // ---- software pipeline over 8 K-chunks of 32 ----
    gather(0, 0);
    CP_COMMIT();

#pragma unroll 1
    for (int c = 0; c < 8; ++c) {
        const int p = c & 1;
        if (c < 7) { gather(c + 1, p ^ 1); CP_COMMIT(); CP_WAIT(1); }
        else       { CP_WAIT(0); }
        __syncthreads();

        const uint32_t uAh = sTiles + (p * 3 + 0) * TILE_BYTES + aOff;
        const uint32_t uAl = sTiles + (p * 3 + 1) * TILE_BYTES + aOff;
        const uint32_t uB  = sTiles + (p * 3 + 2) * TILE_BYTES + bOff;

#pragma unroll
        for (int s = 0; s < 2; ++s) {
            const uint32_t so = (uint32_t)s * 32;
            uint32_t A[4][4], B[4][2];
#pragma unroll
            for (int mi = 0; mi < 4; ++mi)
                ldsm4(A[mi][0], A[mi][1], A[mi][2], A[mi][3],
                      uAh + (uint32_t)mi * 1280 + so);
#pragma unroll
            for (int nj = 0; nj < 2; ++nj)
                ldsm4(B[2 * nj][0], B[2 * nj][1],
                      B[2 * nj + 1][0], B[2 * nj + 1][1],
                      uB + (uint32_t)nj * 1280 + so);
            // chain 1: Ah * B
#pragma unroll
            for (int mi = 0; mi < 4; ++mi)
#pragma unroll
                for (int ni = 0; ni < 4; ++ni)
                    mma16816(acc[mi][ni], A[mi], B[ni]);
            // chain 2: Al * B (reload A regs with low half)
#pragma unroll
            for (int mi = 0; mi < 4; ++mi)
                ldsm4(A[mi][0], A[mi][1], A[mi][2], A[mi][3],
                      uAl + (uint32_t)mi * 1280 + so);
#pragma unroll
            for (int mi = 0; mi < 4; ++mi)
#pragma unroll
                for (int ni = 0; ni < 4; ++ni)
                    mma16816(acc[mi][ni], A[mi], B[ni]);
        }
        __syncthreads();
    }

    // ---- epilogue: bias + ReLU + dot(W2) fused in registers ----
    float b1v[4][2], w2v[4][2];
#pragma unroll
    for (int ni = 0; ni < 4; ++ni) {
        int n0 = warp_n * 32 + ni * 8 + 2 * (lid & 3);
        b1v[ni][0] = s_b1[n0];     b1v[ni][1] = s_b1[n0 + 1];
        w2v[ni][0] = s_w2[n0];     w2v[ni][1] = s_w2[n0 + 1];
    }
#pragma unroll
    for (int mi = 0; mi < 4; ++mi) {
#pragma unroll
        for (int rr = 0; rr < 2; ++rr) {
            float p = 0.0f;
#pragma unroll
            for (int ni = 0; ni < 4; ++ni) {
                float v0 = fmaxf(acc[mi][ni][rr * 2 + 0] + b1v[ni][0], 0.0f);
                float v1 = fmaxf(acc[mi][ni][rr * 2 + 1] + b1v[ni][1], 0.0f);
                p = fmaf(v0, w2v[ni][0], p);
                p = fmaf(v1, w2v[ni][1], p);
            }
            p += __shfl_xor_sync(0xffffffffu, p, 1);
            p += __shfl_xor_sync(0xffffffffu, p, 2);
            if ((lid & 3) == 0) {
                int row = warp_m * 64 + mi * 16 + rr * 8 + (lid >> 2);
                red[row][warp_n] = p;
            }
        }
    }
    __syncthreads();

    if (tid < 128) {
        long long e = e0 + tid;
        if (e < n_edges) {
            out[e] = b2[0] + red[tid][0] + red[tid][1] + red[tid][2] + red[tid][3];
        }
    }
}

// ============================ launch =====================================
extern "C" void kernel_launch(void* const* d_in, const int* in_sizes, int n_in,
                              void* d_out, int out_size)
{
    const float*     z   = (const float*)d_in[0];
    const long long* eli = (const long long*)d_in[1];
    const float*     W1  = (const float*)d_in[2];
    const float*     b1  = (const float*)d_in[3];
    const float*     W2  = (const float*)d_in[4];
    const float*     b2  = (const float*)d_in[5];
    float*           out = (float*)d_out;

    const int n_z = in_sizes[0];
    const int n_edges = in_sizes[1] / 2;
    const int n8 = n_z / 8;
    const int zblocks = (n8 + 255) / 256;
    const int wblocks = (256 * 128 + 255) / 256;

    convert_fused<<<zblocks + wblocks, 256>>>((const float4*)z, W1, n8, zblocks);

    static int configured = 0;
    if (!configured) {
        cudaFuncSetAttribute(edge_mlp_hmma,
                             cudaFuncAttributeMaxDynamicSharedMemorySize, SMEM_TOTAL);
        configured = 1;
    }
    const int grid = (n_edges + 127) / 128;
    edge_mlp_hmma<<<grid, 256, SMEM_TOTAL>>>(eli, b1, W2, b2, out, n_edges);
}

// round 13
// speedup vs baseline: 1.6205x; 1.6205x over previous
#include <cuda_runtime.h>
#include <cuda_fp16.h>
#include <cstdint>

// ============================ device scratch (16B-aligned) ===============
#define N_NODES_MAX 100000
#define DFEAT 128
// each uint4 = 8 fp16
__device__ uint4 g_z_hi4[(size_t)N_NODES_MAX * DFEAT / 8];
__device__ uint4 g_z_lo4[(size_t)N_NODES_MAX * DFEAT / 8];
__device__ uint4 g_w1t4[128 * 256 / 8];      // [n][k] fp16, row = 32 uint4

// ============================ helpers ====================================
__device__ __forceinline__ void mma16816(float* d, const uint32_t* a,
                                         const uint32_t* b) {
    asm volatile(
        "mma.sync.aligned.m16n8k16.row.col.f32.f16.f16.f32 "
        "{%0,%1,%2,%3},{%4,%5,%6,%7},{%8,%9},{%0,%1,%2,%3};"
        : "+f"(d[0]), "+f"(d[1]), "+f"(d[2]), "+f"(d[3])
        : "r"(a[0]), "r"(a[1]), "r"(a[2]), "r"(a[3]), "r"(b[0]), "r"(b[1]));
}
__device__ __forceinline__ void ldsm4(uint32_t& r0, uint32_t& r1,
                                      uint32_t& r2, uint32_t& r3, uint32_t a) {
    asm volatile("ldmatrix.sync.aligned.m8n8.x4.shared.b16 {%0,%1,%2,%3}, [%4];"
                 : "=r"(r0), "=r"(r1), "=r"(r2), "=r"(r3) : "r"(a));
}
__device__ __forceinline__ uint32_t smem_u32(const void* p) {
    uint32_t a;
    asm("{ .reg .u64 t; cvta.to.shared.u64 t, %1; cvt.u32.u64 %0, t; }"
        : "=r"(a) : "l"(p));
    return a;
}
__device__ __forceinline__ void cp_cg16(uint32_t dst, const void* src) {
    asm volatile("cp.async.cg.shared.global [%0], [%1], 16;"
                 :: "r"(dst), "l"(src) : "memory");
}
__device__ __forceinline__ void cp_ca16(uint32_t dst, const void* src) {
    asm volatile("cp.async.ca.shared.global [%0], [%1], 16;"
                 :: "r"(dst), "l"(src) : "memory");
}
#define CP_COMMIT()  asm volatile("cp.async.commit_group;" ::: "memory")
#define CP_WAIT(n)   asm volatile("cp.async.wait_group %0;" :: "n"(n) : "memory")

// ============================ fused conversion kernel ====================
__global__ void convert_fused(const float4* __restrict__ z,
                              const float* __restrict__ W1,
                              int n8, int zblocks) {
    if ((int)blockIdx.x < zblocks) {
        int i = blockIdx.x * 256 + threadIdx.x;
        if (i >= n8) return;
        float4 a = z[2 * i], b = z[2 * i + 1];
        float f[8] = {a.x, a.y, a.z, a.w, b.x, b.y, b.z, b.w};
        unsigned int h[8], l[8];
#pragma unroll
        for (int j = 0; j < 8; ++j) {
            __half hb = __float2half(f[j]);
            float r = f[j] - __half2float(hb);
            __half lb = __float2half(r);
            h[j] = (unsigned int)__half_as_ushort(hb);
            l[j] = (unsigned int)__half_as_ushort(lb);
        }
        g_z_hi4[i] = make_uint4(h[0] | (h[1] << 16), h[2] | (h[3] << 16),
                                h[4] | (h[5] << 16), h[6] | (h[7] << 16));
        g_z_lo4[i] = make_uint4(l[0] | (l[1] << 16), l[2] | (l[3] << 16),
                                l[4] | (l[5] << 16), l[6] | (l[7] << 16));
    } else {
        int i = (blockIdx.x - zblocks) * 256 + threadIdx.x;  // i = k*128 + n
        if (i >= 256 * 128) return;
        int k = i >> 7, n = i & 127;
        reinterpret_cast<__half*>(g_w1t4)[n * 256 + k] = __float2half(W1[i]);
    }
}

// ============================ main kernel ================================
// SMEM tiles: 128 rows x 32 k fp16, row stride 40 halfs (80 B = 20 words)
// 3-stage circular pipeline x 3 tiles (Ah, Al, B) per stage.
#define TILE_BYTES 10240
#define STAGE_BYTES (3 * TILE_BYTES)
#define OFF_TILES  0                    // 9 tiles
#define OFF_ROWS   (9 * TILE_BYTES)     // int[256]
#define OFF_B1     (OFF_ROWS + 1024)    // float[128]
#define OFF_W2     (OFF_B1 + 512)       // float[128]
#define OFF_RED    (OFF_W2 + 512)       // float[128][5]
#define SMEM_TOTAL (OFF_RED + 2560)

__global__ void __launch_bounds__(256, 2)
edge_mlp_hmma(const long long* __restrict__ eli64,
              const float* __restrict__ b1,
              const float* __restrict__ W2v,
              const float* __restrict__ b2,
              float* __restrict__ out,
              int n_edges)
{
    extern __shared__ char dsm[];
    int*   rows = (int*)(dsm + OFF_ROWS);
    float* s_b1 = (float*)(dsm + OFF_B1);
    float* s_w2 = (float*)(dsm + OFF_W2);
    float (*red)[5] = (float(*)[5])(dsm + OFF_RED);

    const int tid = threadIdx.x;
    const int lid = tid & 31;
    const int wid = tid >> 5;
    const int warp_m = wid >> 2;          // 0..1 -> 64 rows each
    const int warp_n = wid & 3;           // 0..3 -> 32 cols each
    const long long e0 = (long long)blockIdx.x * 128;

    // ---- index dtype detection (int64 declared, int32 possible) ----
    const int* eli32 = (const int*)eli64;
    int hi_or = eli32[1] | eli32[3] | eli32[5] | eli32[7]
              | eli32[9] | eli32[11] | eli32[13] | eli32[15];
    const bool is64 = (hi_or == 0);

    if (tid < 128) {
        long long e = e0 + tid;
        if (e >= n_edges) e = 0;
        int rs, rd;
        if (is64) { rs = (int)eli64[e]; rd = (int)eli64[(long long)n_edges + e]; }
        else      { rs = eli32[e];      rd = eli32[(long long)n_edges + e]; }
        rows[tid]       = rs;
        rows[128 + tid] = rd;
    } else {
        int h = tid - 128;
        s_b1[h] = b1[h];
        s_w2[h] = W2v[h];
    }
    __syncthreads();

    // ---- ldmatrix per-lane offsets ----
    const uint32_t sel = (uint32_t)lid >> 3;   // 0..3
    const uint32_t rA  = (uint32_t)lid & 7;
    const uint32_t aOff = ((uint32_t)warp_m * 64 + (sel & 1) * 8 + rA) * 80
                        + (sel >> 1) * 16;           // + mi*1280 + s*32
    const uint32_t bOff = ((uint32_t)warp_n * 32 + (sel >> 1) * 8 + rA) * 80
                        + (sel & 1) * 16;            // + nj*1280 + s*32

    float acc[4][4][4];
#pragma unroll
    for (int mi = 0; mi < 4; ++mi)
#pragma unroll
        for (int ni = 0; ni < 4; ++ni)
#pragma unroll
            for (int qq = 0; qq < 4; ++qq) acc[mi][ni][qq] = 0.0f;

    // gather geometry: 2 threads per row, 32B (2x16B) each
    const int gr  = tid >> 1;
    const int seg = tid & 1;
    const uint32_t smo = (uint32_t)gr * 80 + (uint32_t)seg * 32;
    const uint32_t sTiles = smem_u32(dsm + OFF_TILES);
    const uint32_t sAh0 = sTiles + smo;
    const size_t wa = (size_t)gr * 32 + (size_t)seg * 2;

    auto gather = [&](int c, int st) {
        const int half = c >> 2;
        const int czi  = (c & 3) * 4;
        const uint32_t base = sAh0 + (uint32_t)st * STAGE_BYTES;
        const size_t za = (size_t)rows[half * 128 + gr] * 16 + czi + (size_t)seg * 2;
        cp_cg16(base,                   g_z_hi4 + za);
        cp_cg16(base + 16,              g_z_hi4 + za + 1);
        cp_cg16(base + TILE_BYTES,      g_z_lo4 + za);
        cp_cg16(base + TILE_BYTES + 16, g_z_lo4 + za + 1);
        const size_t wz = wa + (size_t)c * 4;
        cp_ca16(base + 2 * TILE_BYTES,      g_w1t4 + wz);
        cp_ca16(base + 2 * TILE_BYTES + 16, g_w1t4 + wz + 1);
    };

    // ---- 3-stage pipeline over 8 K-chunks of 32, ONE barrier per chunk ----
    gather(0, 0); CP_COMMIT();
    gather(1, 1); CP_COMMIT();

    int stc = 0;     // stage of chunk c
    int stp = 2;     // stage for prefetch (c+2)
#pragma unroll 1
    for (int c = 0; c < 8; ++c) {
        if (c < 7) { CP_WAIT(1); } else { CP_WAIT(0); }
        __syncthreads();
        if (c < 6) { gather(c + 2, stp); CP_COMMIT(); }

        const uint32_t sb = sTiles + (uint32_t)stc * STAGE_BYTES;
        const uint32_t uAh = sb + aOff;
        const uint32_t uAl = sb + TILE_BYTES + aOff;
        const uint32_t uB  = sb + 2 * TILE_BYTES + bOff;

#pragma unroll
        for (int s = 0; s < 2; ++s) {
            const uint32_t so = (uint32_t)s * 32;
            uint32_t A[4][4], Al[4][4], B[4][2];
#pragma unroll
            for (int mi = 0; mi < 4; ++mi)
                ldsm4(A[mi][0], A[mi][1], A[mi][2], A[mi][3],
                      uAh + (uint32_t)mi * 1280 + so);
#pragma unroll
            for (int mi = 0; mi < 4; ++mi)
                ldsm4(Al[mi][0], Al[mi][1], Al[mi][2], Al[mi][3],
                      uAl + (uint32_t)mi * 1280 + so);
#pragma unroll
            for (int nj = 0; nj < 2; ++nj)
                ldsm4(B[2 * nj][0], B[2 * nj][1],
                      B[2 * nj + 1][0], B[2 * nj + 1][1],
                      uB + (uint32_t)nj * 1280 + so);
            // chain 1: Ah * B
#pragma unroll
            for (int mi = 0; mi < 4; ++mi)
#pragma unroll
                for (int ni = 0; ni < 4; ++ni)
                    mma16816(acc[mi][ni], A[mi], B[ni]);
            // chain 2: Al * B (independent registers, no reload)
#pragma unroll
            for (int mi = 0; mi < 4; ++mi)
#pragma unroll
                for (int ni = 0; ni < 4; ++ni)
                    mma16816(acc[mi][ni], Al[mi], B[ni]);
        }
        stc = (stc == 2) ? 0 : stc + 1;
        stp = (stp == 2) ? 0 : stp + 1;
    }

    // ---- epilogue: bias + ReLU + dot(W2) fused in registers ----
    float b1v[4][2], w2v[4][2];
#pragma unroll
    for (int ni = 0; ni < 4; ++ni) {
        int n0 = warp_n * 32 + ni * 8 + 2 * (lid & 3);
        b1v[ni][0] = s_b1[n0];     b1v[ni][1] = s_b1[n0 + 1];
        w2v[ni][0] = s_w2[n0];     w2v[ni][1] = s_w2[n0 + 1];
    }
#pragma unroll
    for (int mi = 0; mi < 4; ++mi) {
#pragma unroll
        for (int rr = 0; rr < 2; ++rr) {
            float p = 0.0f;
#pragma unroll
            for (int ni = 0; ni < 4; ++ni) {
                float v0 = fmaxf(acc[mi][ni][rr * 2 + 0] + b1v[ni][0], 0.0f);
                float v1 = fmaxf(acc[mi][ni][rr * 2 + 1] + b1v[ni][1], 0.0f);
                p = fmaf(v0, w2v[ni][0], p);
                p = fmaf(v1, w2v[ni][1], p);
            }
            p += __shfl_xor_sync(0xffffffffu, p, 1);
            p += __shfl_xor_sync(0xffffffffu, p, 2);
            if ((lid & 3) == 0) {
                int row = warp_m * 64 + mi * 16 + rr * 8 + (lid >> 2);
                red[row][warp_n] = p;
            }
        }
    }
    __syncthreads();

    if (tid < 128) {
        long long e = e0 + tid;
        if (e < n_edges) {
            out[e] = b2[0] + red[tid][0] + red[tid][1] + red[tid][2] + red[tid][3];
        }
    }
}

// ============================ launch =====================================
extern "C" void kernel_launch(void* const* d_in, const int* in_sizes, int n_in,
                              void* d_out, int out_size)
{
    const float*     z   = (const float*)d_in[0];
    const long long* eli = (const long long*)d_in[1];
    const float*     W1  = (const float*)d_in[2];
    const float*     b1  = (const float*)d_in[3];
    const float*     W2  = (const float*)d_in[4];
    const float*     b2  = (const float*)d_in[5];
    float*           out = (float*)d_out;

    const int n_z = in_sizes[0];
    const int n_edges = in_sizes[1] / 2;
    const int n8 = n_z / 8;
    const int zblocks = (n8 + 255) / 256;
    const int wblocks = (256 * 128 + 255) / 256;

    convert_fused<<<zblocks + wblocks, 256>>>((const float4*)z, W1, n8, zblocks);

    static int configured = 0;
    if (!configured) {
        cudaFuncSetAttribute(edge_mlp_hmma,
                             cudaFuncAttributeMaxDynamicSharedMemorySize, SMEM_TOTAL);
        configured = 1;
    }
    const int grid = (n_edges + 127) / 128;
    edge_mlp_hmma<<<grid, 256, SMEM_TOTAL>>>(eli, b1, W2, b2, out, n_edges);
}

// round 14
// speedup vs baseline: 1.9316x; 1.1919x over previous
#include <cuda_runtime.h>
#include <cuda_fp16.h>
#include <cstdint>

// ============================ device scratch (16B-aligned) ===============
#define N_NODES_MAX 100000
#define DFEAT 128
// each uint4 = 8 fp16
__device__ uint4 g_z_hi4[(size_t)N_NODES_MAX * DFEAT / 8];
__device__ uint4 g_z_lo4[(size_t)N_NODES_MAX * DFEAT / 8];
__device__ uint4 g_w1t4[128 * 256 / 8];      // [n][k] fp16, row = 32 uint4

// ============================ helpers ====================================
__device__ __forceinline__ void mma16816(float* d, const uint32_t* a,
                                         const uint32_t* b) {
    asm volatile(
        "mma.sync.aligned.m16n8k16.row.col.f32.f16.f16.f32 "
        "{%0,%1,%2,%3},{%4,%5,%6,%7},{%8,%9},{%0,%1,%2,%3};"
        : "+f"(d[0]), "+f"(d[1]), "+f"(d[2]), "+f"(d[3])
        : "r"(a[0]), "r"(a[1]), "r"(a[2]), "r"(a[3]), "r"(b[0]), "r"(b[1]));
}
__device__ __forceinline__ void ldsm4(uint32_t& r0, uint32_t& r1,
                                      uint32_t& r2, uint32_t& r3, uint32_t a) {
    asm volatile("ldmatrix.sync.aligned.m8n8.x4.shared.b16 {%0,%1,%2,%3}, [%4];"
                 : "=r"(r0), "=r"(r1), "=r"(r2), "=r"(r3) : "r"(a));
}
__device__ __forceinline__ uint32_t smem_u32(const void* p) {
    uint32_t a;
    asm("{ .reg .u64 t; cvta.to.shared.u64 t, %1; cvt.u32.u64 %0, t; }"
        : "=r"(a) : "l"(p));
    return a;
}
__device__ __forceinline__ void cp_cg16(uint32_t dst, const void* src) {
    asm volatile("cp.async.cg.shared.global [%0], [%1], 16;"
                 :: "r"(dst), "l"(src) : "memory");
}
__device__ __forceinline__ void cp_ca16(uint32_t dst, const void* src) {
    asm volatile("cp.async.ca.shared.global [%0], [%1], 16;"
                 :: "r"(dst), "l"(src) : "memory");
}
#define CP_COMMIT()  asm volatile("cp.async.commit_group;" ::: "memory")
#define CP_WAIT(n)   asm volatile("cp.async.wait_group %0;" :: "n"(n) : "memory")

// ============================ fused conversion kernel ====================
__global__ void convert_fused(const float4* __restrict__ z,
                              const float* __restrict__ W1,
                              int n8, int zblocks) {
    if ((int)blockIdx.x < zblocks) {
        int i = blockIdx.x * 256 + threadIdx.x;
        if (i >= n8) return;
        float4 a = z[2 * i], b = z[2 * i + 1];
        float f[8] = {a.x, a.y, a.z, a.w, b.x, b.y, b.z, b.w};
        unsigned int h[8], l[8];
#pragma unroll
        for (int j = 0; j < 8; ++j) {
            __half hb = __float2half(f[j]);
            float r = f[j] - __half2float(hb);
            __half lb = __float2half(r);
            h[j] = (unsigned int)__half_as_ushort(hb);
            l[j] = (unsigned int)__half_as_ushort(lb);
        }
        g_z_hi4[i] = make_uint4(h[0] | (h[1] << 16), h[2] | (h[3] << 16),
                                h[4] | (h[5] << 16), h[6] | (h[7] << 16));
        g_z_lo4[i] = make_uint4(l[0] | (l[1] << 16), l[2] | (l[3] << 16),
                                l[4] | (l[5] << 16), l[6] | (l[7] << 16));
    } else {
        int i = (blockIdx.x - zblocks) * 256 + threadIdx.x;  // i = k*128 + n
        if (i >= 256 * 128) return;
        int k = i >> 7, n = i & 127;
        reinterpret_cast<__half*>(g_w1t4)[n * 256 + k] = __float2half(W1[i]);
    }
}

// ============================ main kernel ================================
// SMEM tiles: 128 rows x 32 k fp16, row stride 40 halfs (80 B = 20 words)
// 3-stage circular pipeline x 3 tiles (Ah, Al, B) per stage.
#define TILE_BYTES 10240
#define STAGE_BYTES (3 * TILE_BYTES)
#define OFF_TILES  0                    // 9 tiles
#define OFF_ROWS   (9 * TILE_BYTES)     // int[256]
#define OFF_B1     (OFF_ROWS + 1024)    // float[128]
#define OFF_W2     (OFF_B1 + 512)       // float[128]
#define OFF_RED    (OFF_W2 + 512)       // float[128][3]
#define SMEM_TOTAL (OFF_RED + 1536)

__global__ void __launch_bounds__(256, 2)
edge_mlp_hmma(const long long* __restrict__ eli64,
              const float* __restrict__ b1,
              const float* __restrict__ W2v,
              const float* __restrict__ b2,
              float* __restrict__ out,
              int n_edges)
{
    extern __shared__ char dsm[];
    int*   rows = (int*)(dsm + OFF_ROWS);
    float* s_b1 = (float*)(dsm + OFF_B1);
    float* s_w2 = (float*)(dsm + OFF_W2);
    float (*red)[3] = (float(*)[3])(dsm + OFF_RED);

    const int tid = threadIdx.x;
    const int lid = tid & 31;
    const int wid = tid >> 5;
    const int warp_m = wid >> 1;          // 0..3 -> 32 rows each
    const int warp_n = wid & 1;           // 0..1 -> 64 cols each
    const long long e0 = (long long)blockIdx.x * 128;

    // ---- index dtype detection (int64 declared, int32 possible) ----
    const int* eli32 = (const int*)eli64;
    int hi_or = eli32[1] | eli32[3] | eli32[5] | eli32[7]
              | eli32[9] | eli32[11] | eli32[13] | eli32[15];
    const bool is64 = (hi_or == 0);

    if (tid < 128) {
        long long e = e0 + tid;
        if (e >= n_edges) e = 0;
        int rs, rd;
        if (is64) { rs = (int)eli64[e]; rd = (int)eli64[(long long)n_edges + e]; }
        else      { rs = eli32[e];      rd = eli32[(long long)n_edges + e]; }
        rows[tid]       = rs;
        rows[128 + tid] = rd;
    } else {
        int h = tid - 128;
        s_b1[h] = b1[h];
        s_w2[h] = W2v[h];
    }
    __syncthreads();

    // ---- ldmatrix per-lane offsets ----
    const uint32_t sel = (uint32_t)lid >> 3;   // 0..3
    const uint32_t rA  = (uint32_t)lid & 7;
    // A (m16k16): {rows0-7 k0, rows8-15 k0, rows0-7 k8, rows8-15 k8}
    const uint32_t aOff = ((uint32_t)warp_m * 32 + (sel & 1) * 8 + rA) * 80
                        + (sel >> 1) * 16;           // + mi*1280 + s*32
    // B ([n][k]): {n0-7 k0, n0-7 k8, n8-15 k0, n8-15 k8} per nj pair
    const uint32_t bOff = ((uint32_t)warp_n * 64 + (sel >> 1) * 8 + rA) * 80
                        + (sel & 1) * 16;            // + nj*1280 + s*32

    float acc[2][8][4];
#pragma unroll
    for (int mi = 0; mi < 2; ++mi)
#pragma unroll
        for (int ni = 0; ni < 8; ++ni)
#pragma unroll
            for (int qq = 0; qq < 4; ++qq) acc[mi][ni][qq] = 0.0f;

    // gather geometry: 2 threads per row, 32B (2x16B) each
    const int gr  = tid >> 1;
    const int seg = tid & 1;
    const uint32_t smo = (uint32_t)gr * 80 + (uint32_t)seg * 32;
    const uint32_t sTiles = smem_u32(dsm + OFF_TILES);
    const uint32_t sAh0 = sTiles + smo;
    const size_t wa = (size_t)gr * 32 + (size_t)seg * 2;

    auto gather = [&](int c, int st) {
        const int half = c >> 2;
        const int czi  = (c & 3) * 4;
        const uint32_t base = sAh0 + (uint32_t)st * STAGE_BYTES;
        const size_t za = (size_t)rows[half * 128 + gr] * 16 + czi + (size_t)seg * 2;
        cp_cg16(base,                   g_z_hi4 + za);
        cp_cg16(base + 16,              g_z_hi4 + za + 1);
        if (c < 4) {   // A-lo chain only for first half of K
            cp_cg16(base + TILE_BYTES,      g_z_lo4 + za);
            cp_cg16(base + TILE_BYTES + 16, g_z_lo4 + za + 1);
        }
        const size_t wz = wa + (size_t)c * 4;
        cp_ca16(base + 2 * TILE_BYTES,      g_w1t4 + wz);
        cp_ca16(base + 2 * TILE_BYTES + 16, g_w1t4 + wz + 1);
    };

    // ---- 3-stage pipeline over 8 K-chunks of 32, ONE barrier per chunk ----
    gather(0, 0); CP_COMMIT();
    gather(1, 1); CP_COMMIT();

    int stc = 0;     // stage of chunk c
    int stp = 2;     // stage for prefetch (c+2)
#pragma unroll 1
    for (int c = 0; c < 8; ++c) {
        if (c < 7) { CP_WAIT(1); } else { CP_WAIT(0); }
        __syncthreads();
        if (c < 6) { gather(c + 2, stp); CP_COMMIT(); }

        const uint32_t sb = sTiles + (uint32_t)stc * STAGE_BYTES;
        const uint32_t uAh = sb + aOff;
        const uint32_t uAl = sb + TILE_BYTES + aOff;
        const uint32_t uB  = sb + 2 * TILE_BYTES + bOff;
        const bool lo = (c < 4);

#pragma unroll
        for (int s = 0; s < 2; ++s) {
            const uint32_t so = (uint32_t)s * 32;
            uint32_t A[2][4], Al[2][4], B[8][2];
#pragma unroll
            for (int mi = 0; mi < 2; ++mi)
                ldsm4(A[mi][0], A[mi][1], A[mi][2], A[mi][3],
                      uAh + (uint32_t)mi * 1280 + so);
            if (lo) {
#pragma unroll
                for (int mi = 0; mi < 2; ++mi)
                    ldsm4(Al[mi][0], Al[mi][1], Al[mi][2], Al[mi][3],
                          uAl + (uint32_t)mi * 1280 + so);
            }
#pragma unroll
            for (int nj = 0; nj < 4; ++nj)
                ldsm4(B[2 * nj][0], B[2 * nj][1],
                      B[2 * nj + 1][0], B[2 * nj + 1][1],
                      uB + (uint32_t)nj * 1280 + so);
            // chain 1: Ah * B
#pragma unroll
            for (int mi = 0; mi < 2; ++mi)
#pragma unroll
                for (int ni = 0; ni < 8; ++ni)
                    mma16816(acc[mi][ni], A[mi], B[ni]);
            // chain 2: Al * B (first half of K only)
            if (lo) {
#pragma unroll
                for (int mi = 0; mi < 2; ++mi)
#pragma unroll
                    for (int ni = 0; ni < 8; ++ni)
                        mma16816(acc[mi][ni], Al[mi], B[ni]);
            }
        }
        stc = (stc == 2) ? 0 : stc + 1;
        stp = (stp == 2) ? 0 : stp + 1;
    }

    // ---- epilogue: bias + ReLU + dot(W2) fused in registers ----
    float b1v[8][2], w2v[8][2];
#pragma unroll
    for (int ni = 0; ni < 8; ++ni) {
        int n0 = warp_n * 64 + ni * 8 + 2 * (lid & 3);
        b1v[ni][0] = s_b1[n0];     b1v[ni][1] = s_b1[n0 + 1];
        w2v[ni][0] = s_w2[n0];     w2v[ni][1] = s_w2[n0 + 1];
    }
#pragma unroll
    for (int mi = 0; mi < 2; ++mi) {
#pragma unroll
        for (int rr = 0; rr < 2; ++rr) {
            float p = 0.0f;
#pragma unroll
            for (int ni = 0; ni < 8; ++ni) {
                float v0 = fmaxf(acc[mi][ni][rr * 2 + 0] + b1v[ni][0], 0.0f);
                float v1 = fmaxf(acc[mi][ni][rr * 2 + 1] + b1v[ni][1], 0.0f);
                p = fmaf(v0, w2v[ni][0], p);
                p = fmaf(v1, w2v[ni][1], p);
            }
            p += __shfl_xor_sync(0xffffffffu, p, 1);
            p += __shfl_xor_sync(0xffffffffu, p, 2);
            if ((lid & 3) == 0) {
                int row = warp_m * 32 + mi * 16 + rr * 8 + (lid >> 2);
                red[row][warp_n] = p;
            }
        }
    }
    __syncthreads();

    if (tid < 128) {
        long long e = e0 + tid;
        if (e < n_edges) {
            out[e] = b2[0] + red[tid][0] + red[tid][1];
        }
    }
}

// ============================ launch =====================================
extern "C" void kernel_launch(void* const* d_in, const int* in_sizes, int n_in,
                              void* d_out, int out_size)
{
    const float*     z   = (const float*)d_in[0];
    const long long* eli = (const long long*)d_in[1];
    const float*     W1  = (const float*)d_in[2];
    const float*     b1  = (const float*)d_in[3];
    const float*     W2  = (const float*)d_in[4];
    const float*     b2  = (const float*)d_in[5];
    float*           out = (float*)d_out;

    const int n_z = in_sizes[0];
    const int n_edges = in_sizes[1] / 2;
    const int n8 = n_z / 8;
    const int zblocks = (n8 + 255) / 256;
    const int wblocks = (256 * 128 + 255) / 256;

    convert_fused<<<zblocks + wblocks, 256>>>((const float4*)z, W1, n8, zblocks);

    static int configured = 0;
    if (!configured) {
        cudaFuncSetAttribute(edge_mlp_hmma,
                             cudaFuncAttributeMaxDynamicSharedMemorySize, SMEM_TOTAL);
        configured = 1;
    }
    const int grid = (n_edges + 127) / 128;
    edge_mlp_hmma<<<grid, 256, SMEM_TOTAL>>>(eli, b1, W2, b2, out, n_edges);
}

// round 16
// speedup vs baseline: 2.4487x; 1.2677x over previous
#include <cuda_runtime.h>
#include <cuda_fp16.h>
#include <cstdint>

// ============================ device scratch (16B-aligned) ===============
#define N_NODES_MAX 100000
#define DFEAT 128
// each uint4 = 8 fp16
__device__ uint4 g_z_hi4[(size_t)N_NODES_MAX * DFEAT / 8];
__device__ uint4 g_w1t4[128 * 256 / 8];      // [n][k] fp16, row = 32 uint4

// ============================ helpers ====================================
__device__ __forceinline__ void mma16816(float* d, const uint32_t* a,
                                         const uint32_t* b) {
    asm volatile(
        "mma.sync.aligned.m16n8k16.row.col.f32.f16.f16.f32 "
        "{%0,%1,%2,%3},{%4,%5,%6,%7},{%8,%9},{%0,%1,%2,%3};"
        : "+f"(d[0]), "+f"(d[1]), "+f"(d[2]), "+f"(d[3])
        : "r"(a[0]), "r"(a[1]), "r"(a[2]), "r"(a[3]), "r"(b[0]), "r"(b[1]));
}
__device__ __forceinline__ void ldsm4(uint32_t& r0, uint32_t& r1,
                                      uint32_t& r2, uint32_t& r3, uint32_t a) {
    asm volatile("ldmatrix.sync.aligned.m8n8.x4.shared.b16 {%0,%1,%2,%3}, [%4];"
                 : "=r"(r0), "=r"(r1), "=r"(r2), "=r"(r3) : "r"(a));
}
__device__ __forceinline__ uint32_t smem_u32(const void* p) {
    uint32_t a;
    asm("{ .reg .u64 t; cvta.to.shared.u64 t, %1; cvt.u32.u64 %0, t; }"
        : "=r"(a) : "l"(p));
    return a;
}
__device__ __forceinline__ void cp_cg16(uint32_t dst, const void* src) {
    asm volatile("cp.async.cg.shared.global [%0], [%1], 16;"
                 :: "r"(dst), "l"(src) : "memory");
}
__device__ __forceinline__ void cp_ca16(uint32_t dst, const void* src) {
    asm volatile("cp.async.ca.shared.global [%0], [%1], 16;"
                 :: "r"(dst), "l"(src) : "memory");
}
#define CP_COMMIT()  asm volatile("cp.async.commit_group;" ::: "memory")
#define CP_WAIT(n)   asm volatile("cp.async.wait_group %0;" :: "n"(n) : "memory")

// ============================ fused conversion kernel ====================
__global__ void convert_fused(const float4* __restrict__ z,
                              const float* __restrict__ W1,
                              int n8, int zblocks) {
    if ((int)blockIdx.x < zblocks) {
        int i = blockIdx.x * 256 + threadIdx.x;
        if (i >= n8) return;
        float4 a = z[2 * i], b = z[2 * i + 1];
        float f[8] = {a.x, a.y, a.z, a.w, b.x, b.y, b.z, b.w};
        unsigned int h[8];
#pragma unroll
        for (int j = 0; j < 8; ++j)
            h[j] = (unsigned int)__half_as_ushort(__float2half(f[j]));
        g_z_hi4[i] = make_uint4(h[0] | (h[1] << 16), h[2] | (h[3] << 16),
                                h[4] | (h[5] << 16), h[6] | (h[7] << 16));
    } else {
        int i = (blockIdx.x - zblocks) * 256 + threadIdx.x;  // i = k*128 + n
        if (i >= 256 * 128) return;
        int k = i >> 7, n = i & 127;
        reinterpret_cast<__half*>(g_w1t4)[n * 256 + k] = __float2half(W1[i]);
    }
}

// ============================ main kernel ================================
// SMEM tiles: 128 rows x 32 k fp16, row stride 40 halfs (80 B = 20 words)
// 3-stage circular pipeline x 2 tiles (A, B) per stage.
#define TILE_BYTES 10240
#define STAGE_BYTES (2 * TILE_BYTES)
#define OFF_TILES  0                    // 6 tiles
#define OFF_ROWS   (6 * TILE_BYTES)     // int[256]
#define OFF_B1     (OFF_ROWS + 1024)    // float[128]
#define OFF_W2     (OFF_B1 + 512)       // float[128]
#define OFF_RED    (OFF_W2 + 512)       // float[128][3]
#define SMEM_TOTAL (OFF_RED + 1536)

__global__ void __launch_bounds__(256, 2)
edge_mlp_hmma(const long long* __restrict__ eli64,
              const float* __restrict__ b1,
              const float* __restrict__ W2v,
              const float* __restrict__ b2,
              float* __restrict__ out,
              int n_edges)
{
    extern __shared__ char dsm[];
    int*   rows = (int*)(dsm + OFF_ROWS);
    float* s_b1 = (float*)(dsm + OFF_B1);
    float* s_w2 = (float*)(dsm + OFF_W2);
    float (*red)[3] = (float(*)[3])(dsm + OFF_RED);

    const int tid = threadIdx.x;
    const int lid = tid & 31;
    const int wid = tid >> 5;
    const int warp_m = wid >> 1;          // 0..3 -> 32 rows each
    const int warp_n = wid & 1;           // 0..1 -> 64 cols each
    const long long e0 = (long long)blockIdx.x * 128;

    // ---- index dtype detection (int64 declared, int32 possible) ----
    const int* eli32 = (const int*)eli64;
    int hi_or = eli32[1] | eli32[3] | eli32[5] | eli32[7]
              | eli32[9] | eli32[11] | eli32[13] | eli32[15];
    const bool is64 = (hi_or == 0);

    if (tid < 128) {
        long long e = e0 + tid;
        if (e >= n_edges) e = 0;
        int rs, rd;
        if (is64) { rs = (int)eli64[e]; rd = (int)eli64[(long long)n_edges + e]; }
        else      { rs = eli32[e];      rd = eli32[(long long)n_edges + e]; }
        rows[tid]       = rs;
        rows[128 + tid] = rd;
    } else {
        int h = tid - 128;
        s_b1[h] = b1[h];
        s_w2[h] = W2v[h];
    }
    __syncthreads();

    // ---- ldmatrix per-lane offsets ----
    const uint32_t sel = (uint32_t)lid >> 3;   // 0..3
    const uint32_t rA  = (uint32_t)lid & 7;
    // A (m16k16): {rows0-7 k0, rows8-15 k0, rows0-7 k8, rows8-15 k8}
    const uint32_t aOff = ((uint32_t)warp_m * 32 + (sel & 1) * 8 + rA) * 80
                        + (sel >> 1) * 16;           // + mi*1280 + s*32
    // B ([n][k]): {n0-7 k0, n0-7 k8, n8-15 k0, n8-15 k8} per nj pair
    const uint32_t bOff = ((uint32_t)warp_n * 64 + (sel >> 1) * 8 + rA) * 80
                        + (sel & 1) * 16;            // + nj*1280 + s*32

    float acc[2][8][4];
#pragma unroll
    for (int mi = 0; mi < 2; ++mi)
#pragma unroll
        for (int ni = 0; ni < 8; ++ni)
#pragma unroll
            for (int qq = 0; qq < 4; ++qq) acc[mi][ni][qq] = 0.0f;

    // gather geometry: 2 threads per row, 32B (2x16B) each
    const int gr  = tid >> 1;
    const int seg = tid & 1;
    const uint32_t smo = (uint32_t)gr * 80 + (uint32_t)seg * 32;
    const uint32_t sTiles = smem_u32(dsm + OFF_TILES);
    const uint32_t sA0 = sTiles + smo;
    const size_t wa = (size_t)gr * 32 + (size_t)seg * 2;

    auto gather = [&](int c, int st) {
        const int half = c >> 2;
        const int czi  = (c & 3) * 4;
        const uint32_t base = sA0 + (uint32_t)st * STAGE_BYTES;
        const size_t za = (size_t)rows[half * 128 + gr] * 16 + czi + (size_t)seg * 2;
        cp_cg16(base,                   g_z_hi4 + za);
        cp_cg16(base + 16,              g_z_hi4 + za + 1);
        const size_t wz = wa + (size_t)c * 4;
        cp_ca16(base + TILE_BYTES,      g_w1t4 + wz);
        cp_ca16(base + TILE_BYTES + 16, g_w1t4 + wz + 1);
    };

    // ---- 3-stage pipeline over 8 K-chunks of 32, ONE barrier per chunk ----
    gather(0, 0); CP_COMMIT();
    gather(1, 1); CP_COMMIT();

    int stc = 0;     // stage of chunk c
    int stp = 2;     // stage for prefetch (c+2)
#pragma unroll 1
    for (int c = 0; c < 8; ++c) {
        if (c < 7) { CP_WAIT(1); } else { CP_WAIT(0); }
        __syncthreads();
        if (c < 6) { gather(c + 2, stp); CP_COMMIT(); }

        const uint32_t sb = sTiles + (uint32_t)stc * STAGE_BYTES;
        const uint32_t uA = sb + aOff;
        const uint32_t uB = sb + TILE_BYTES + bOff;

#pragma unroll
        for (int s = 0; s < 2; ++s) {
            const uint32_t so = (uint32_t)s * 32;
            uint32_t A[2][4], B[8][2];
#pragma unroll
            for (int mi = 0; mi < 2; ++mi)
                ldsm4(A[mi][0], A[mi][1], A[mi][2], A[mi][3],
                      uA + (uint32_t)mi * 1280 + so);
#pragma unroll
            for (int nj = 0; nj < 4; ++nj)
                ldsm4(B[2 * nj][0], B[2 * nj][1],
                      B[2 * nj + 1][0], B[2 * nj + 1][1],
                      uB + (uint32_t)nj * 1280 + so);
#pragma unroll
            for (int mi = 0; mi < 2; ++mi)
#pragma unroll
                for (int ni = 0; ni < 8; ++ni)
                    mma16816(acc[mi][ni], A[mi], B[ni]);
        }
        stc = (stc == 2) ? 0 : stc + 1;
        stp = (stp == 2) ? 0 : stp + 1;
    }

    // ---- epilogue: bias + ReLU + dot(W2) fused in registers ----
    float b1v[8][2], w2v[8][2];
#pragma unroll
    for (int ni = 0; ni < 8; ++ni) {
        int n0 = warp_n * 64 + ni * 8 + 2 * (lid & 3);
        b1v[ni][0] = s_b1[n0];     b1v[ni][1] = s_b1[n0 + 1];
        w2v[ni][0] = s_w2[n0];     w2v[ni][1] = s_w2[n0 + 1];
    }
#pragma unroll
    for (int mi = 0; mi < 2; ++mi) {
#pragma unroll
        for (int rr = 0; rr < 2; ++rr) {
            float p = 0.0f;
#pragma unroll
            for (int ni = 0; ni < 8; ++ni) {
                float v0 = fmaxf(acc[mi][ni][rr * 2 + 0] + b1v[ni][0], 0.0f);
                float v1 = fmaxf(acc[mi][ni][rr * 2 + 1] + b1v[ni][1], 0.0f);
                p = fmaf(v0, w2v[ni][0], p);
                p = fmaf(v1, w2v[ni][1], p);
            }
            p += __shfl_xor_sync(0xffffffffu, p, 1);
            p += __shfl_xor_sync(0xffffffffu, p, 2);
            if ((lid & 3) == 0) {
                int row = warp_m * 32 + mi * 16 + rr * 8 + (lid >> 2);
                red[row][warp_n] = p;
            }
        }
    }
    __syncthreads();

    if (tid < 128) {
        long long e = e0 + tid;
        if (e < n_edges) {
            out[e] = b2[0] + red[tid][0] + red[tid][1];
        }
    }
}

// ============================ launch =====================================
extern "C" void kernel_launch(void* const* d_in, const int* in_sizes, int n_in,
                              void* d_out, int out_size)
{
    const float*     z   = (const float*)d_in[0];
    const long long* eli = (const long long*)d_in[1];
    const float*     W1  = (const float*)d_in[2];
    const float*     b1  = (const float*)d_in[3];
    const float*     W2  = (const float*)d_in[4];
    const float*     b2  = (const float*)d_in[5];
    float*           out = (float*)d_out;

    const int n_z = in_sizes[0];
    const int n_edges = in_sizes[1] / 2;
    const int n8 = n_z / 8;
    const int zblocks = (n8 + 255) / 256;
    const int wblocks = (256 * 128 + 255) / 256;

    convert_fused<<<zblocks + wblocks, 256>>>((const float4*)z, W1, n8, zblocks);

    static int configured = 0;
    if (!configured) {
        cudaFuncSetAttribute(edge_mlp_hmma,
                             cudaFuncAttributeMaxDynamicSharedMemorySize, SMEM_TOTAL);
        configured = 1;
    }
    const int grid = (n_edges + 127) / 128;
    edge_mlp_hmma<<<grid, 256, SMEM_TOTAL>>>(eli, b1, W2, b2, out, n_edges);
}